// round 4
// baseline (speedup 1.0000x reference)
#include <cuda_runtime.h>
#include <math.h>

#define BB 2
#define SS 1024
#define DM 1024
#define NH 16
#define HD 64
#define FFD 4096
#define NL 12
#define RH 128
#define MM (BB*SS)    /* 2048 rows */
#define NZ (BB*NH)    /* 32 (b,h) batches */

// ---------------- scratch (device globals: allocation-free contract) ----------------
__device__ float g_h  [MM*DM];
__device__ float g_h1 [MM*DM];
__device__ float g_ht [MM*DM];
__device__ float g_q  [MM*DM];
__device__ float g_k  [MM*DM];
__device__ float g_v  [MM*DM];
__device__ float g_att[MM*DM];
__device__ float g_ff [MM*FFD];
__device__ float g_t2 [MM*DM];
__device__ float g_scores[(size_t)NZ*SS*SS];   // 128 MB
__device__ int   g_skip[MM];
__device__ int   g_cnt[3];

// ---------------- small kernels ----------------
__global__ void k_reset() { g_cnt[0]=0; g_cnt[1]=0; g_cnt[2]=0; }

__global__ __launch_bounds__(256) void k_embed(const int* __restrict__ x,
                                               const float* __restrict__ emb) {
    int row = blockIdx.x;
    int tok = x[row];
    int s   = row & (SS-1);
    const float* e = emb + (size_t)tok * DM;
    for (int d = threadIdx.x; d < DM; d += 256) {
        int p = d >> 1;
        float freq = expf((float)(2*p) * (-9.210340371976184f / 1024.f));
        float ang  = (float)s * freq;
        float pe   = (d & 1) ? cosf(ang) : sinf(ang);
        g_h[row*DM + d] = e[d] * 32.f + pe;   // sqrt(1024) = 32
    }
}

// router: one block per token row. rh = relu(h@W1+b1); rlog = rh@W2+b2; argmax.
__global__ __launch_bounds__(128) void k_router(const float* __restrict__ h,
        const float* __restrict__ W1, const float* __restrict__ b1,
        const float* __restrict__ W2, const float* __restrict__ b2) {
    int row = blockIdx.x;
    int tid = threadIdx.x;
    __shared__ float sh[DM];
    __shared__ float srh[RH];
    __shared__ float slog[3];
    for (int c = tid; c < DM; c += 128) sh[c] = h[row*DM + c];
    __syncthreads();
    float acc = 0.f;
    #pragma unroll 8
    for (int c = 0; c < DM; c++) acc += sh[c] * W1[c*RH + tid];
    srh[tid] = fmaxf(acc + b1[tid], 0.f);
    __syncthreads();
    if (tid < 3) {
        float s = 0.f;
        for (int j = 0; j < RH; j++) s += srh[j] * W2[j*3 + tid];
        slog[tid] = s + b2[tid];
    }
    __syncthreads();
    if (tid == 0) {
        int a = 0; float best = slog[0];
        if (slog[1] > best) { best = slog[1]; a = 1; }
        if (slog[2] > best) { a = 2; }
        g_skip[row] = (a == 0);
        atomicAdd(&g_cnt[a], 1);
    }
}

// ---------------- generic fp32 GEMM: C[MxN] = A[MxK] @ B[KxN] + bias ----------------
// MODE 0: plain store   MODE 1: qkv remap to [B,H,S,hd]   MODE 2: relu
template<int MODE>
__global__ __launch_bounds__(256) void k_sgemm(const float* __restrict__ A,
        const float* __restrict__ B, const float* __restrict__ bias,
        float* __restrict__ C, int M, int N, int K) {
    const int BM=128, BN=128, BK=8;
    __shared__ float As[BK][BM];
    __shared__ float Bs[BK][BN];
    int tid = threadIdx.x;
    int tr = tid >> 4, tc = tid & 15;
    int aRow = tid >> 1, aCol = (tid & 1) << 2;
    int bRow = tid >> 5, bCol = (tid & 31) << 2;
    const float* Ab = A + (size_t)(blockIdx.y * BM) * K;
    const float* Bb = B + blockIdx.x * BN;
    float acc[8][8] = {};
    for (int kk = 0; kk < K; kk += BK) {
        float4 a4 = *reinterpret_cast<const float4*>(Ab + (size_t)aRow*K + kk + aCol);
        As[aCol+0][aRow]=a4.x; As[aCol+1][aRow]=a4.y;
        As[aCol+2][aRow]=a4.z; As[aCol+3][aRow]=a4.w;
        float4 b4 = *reinterpret_cast<const float4*>(Bb + (size_t)(kk+bRow)*N + bCol);
        *reinterpret_cast<float4*>(&Bs[bRow][bCol]) = b4;
        __syncthreads();
        #pragma unroll
        for (int k2 = 0; k2 < BK; k2++) {
            float ra[8], rb[8];
            *reinterpret_cast<float4*>(ra  ) = *reinterpret_cast<const float4*>(&As[k2][tr*8  ]);
            *reinterpret_cast<float4*>(ra+4) = *reinterpret_cast<const float4*>(&As[k2][tr*8+4]);
            *reinterpret_cast<float4*>(rb  ) = *reinterpret_cast<const float4*>(&Bs[k2][tc*8  ]);
            *reinterpret_cast<float4*>(rb+4) = *reinterpret_cast<const float4*>(&Bs[k2][tc*8+4]);
            #pragma unroll
            for (int i=0;i<8;i++) {
                #pragma unroll
                for (int j=0;j<8;j++) acc[i][j] += ra[i]*rb[j];
            }
        }
        __syncthreads();
    }
    int m0 = blockIdx.y*BM + tr*8;
    int n0 = blockIdx.x*BN + tc*8;
    #pragma unroll
    for (int i=0;i<8;i++) {
        int m = m0 + i;
        #pragma unroll
        for (int j=0;j<8;j++) {
            int n = n0 + j;
            float val = acc[i][j] + bias[n];
            if (MODE == 2) val = fmaxf(val, 0.f);
            if (MODE == 1) {
                int b = m >> 10, s2 = m & 1023, hh = n >> 6, d = n & 63;
                C[(size_t)(((b*NH + hh)*SS) + s2)*HD + d] = val;
            } else {
                C[(size_t)m*N + n] = val;
            }
        }
    }
}

// ---------------- attention: scores = q@k^T / 8 (causal blocks only) ----------------
__global__ __launch_bounds__(256) void k_scores() {
    int z = blockIdx.z;
    int row0 = blockIdx.y*64, col0 = blockIdx.x*64;
    if (col0 > row0 + 63) return;       // fully above diagonal: never read
    const float* Q  = g_q + (size_t)z*SS*HD;
    const float* Kp = g_k + (size_t)z*SS*HD;
    float* out = g_scores + (size_t)z*SS*SS;
    __shared__ float Qs[16][64];
    __shared__ float Ks[16][64];
    int tid = threadIdx.x;
    int lr = tid >> 2, lc = (tid & 3) << 2;
    int tr = tid >> 4, tc = tid & 15;
    float acc[4][4] = {};
    for (int kk = 0; kk < HD; kk += 16) {
        float4 q4 = *reinterpret_cast<const float4*>(Q  + (size_t)(row0+lr)*HD + kk + lc);
        Qs[lc+0][lr]=q4.x; Qs[lc+1][lr]=q4.y; Qs[lc+2][lr]=q4.z; Qs[lc+3][lr]=q4.w;
        float4 k4 = *reinterpret_cast<const float4*>(Kp + (size_t)(col0+lr)*HD + kk + lc);
        Ks[lc+0][lr]=k4.x; Ks[lc+1][lr]=k4.y; Ks[lc+2][lr]=k4.z; Ks[lc+3][lr]=k4.w;
        __syncthreads();
        #pragma unroll
        for (int k2 = 0; k2 < 16; k2++) {
            float ra[4], rb[4];
            *reinterpret_cast<float4*>(ra) = *reinterpret_cast<const float4*>(&Qs[k2][tr*4]);
            *reinterpret_cast<float4*>(rb) = *reinterpret_cast<const float4*>(&Ks[k2][tc*4]);
            #pragma unroll
            for (int i=0;i<4;i++) {
                #pragma unroll
                for (int j=0;j<4;j++) acc[i][j] += ra[i]*rb[j];
            }
        }
        __syncthreads();
    }
    #pragma unroll
    for (int i=0;i<4;i++) {
        #pragma unroll
        for (int j=0;j<4;j++)
            out[(size_t)(row0 + tr*4 + i)*SS + col0 + tc*4 + j] = acc[i][j]*0.125f;
    }
}

// row softmax, causal: only k<=q valid; zero the tail so PV can run dense
__global__ __launch_bounds__(256) void k_softmax() {
    int r = blockIdx.x;
    int L = (r & (SS-1)) + 1;
    float* row = g_scores + (size_t)r*SS;
    __shared__ float buf[SS];
    __shared__ float red[8];
    int tid = threadIdx.x;
    float mx = -INFINITY;
    for (int c = tid; c < L; c += 256) { float v = row[c]; buf[c] = v; mx = fmaxf(mx, v); }
    for (int o=16;o;o>>=1) mx = fmaxf(mx, __shfl_xor_sync(0xffffffffu, mx, o));
    if ((tid&31)==0) red[tid>>5] = mx;
    __syncthreads();
    mx = red[0];
    #pragma unroll
    for (int i=1;i<8;i++) mx = fmaxf(mx, red[i]);
    float s = 0.f;
    for (int c = tid; c < L; c += 256) { float e = expf(buf[c]-mx); buf[c]=e; s += e; }
    __syncthreads();
    for (int o=16;o;o>>=1) s += __shfl_xor_sync(0xffffffffu, s, o);
    if ((tid&31)==0) red[tid>>5] = s;
    __syncthreads();
    s = red[0];
    #pragma unroll
    for (int i=1;i<8;i++) s += red[i];
    for (int c = tid; c < SS; c += 256) row[c] = (c < L) ? buf[c]/s : 0.f;
}

// attn @ v  -> g_att in [B,S,D] layout.  K loop truncated: probs zero past row0+63.
__global__ __launch_bounds__(256) void k_pv() {
    int z = blockIdx.z;
    int row0 = blockIdx.x*64;
    const float* P = g_scores + (size_t)z*SS*SS;
    const float* V = g_v      + (size_t)z*SS*HD;
    __shared__ float Ps[16][64];
    __shared__ float Vs[16][64];
    int tid = threadIdx.x;
    int pr = tid >> 2, pc = (tid & 3) << 2;
    int vr = tid >> 4, vc = (tid & 15) << 2;
    int tr = tid >> 4, tc = tid & 15;
    float acc[4][4] = {};
    int kmax = row0 + 64;
    for (int kk = 0; kk < kmax; kk += 16) {
        float4 p4 = *reinterpret_cast<const float4*>(P + (size_t)(row0+pr)*SS + kk + pc);
        Ps[pc+0][pr]=p4.x; Ps[pc+1][pr]=p4.y; Ps[pc+2][pr]=p4.z; Ps[pc+3][pr]=p4.w;
        float4 v4 = *reinterpret_cast<const float4*>(V + (size_t)(kk+vr)*HD + vc);
        *reinterpret_cast<float4*>(&Vs[vr][vc]) = v4;
        __syncthreads();
        #pragma unroll
        for (int k2 = 0; k2 < 16; k2++) {
            float ra[4], rb[4];
            *reinterpret_cast<float4*>(ra) = *reinterpret_cast<const float4*>(&Ps[k2][tr*4]);
            *reinterpret_cast<float4*>(rb) = *reinterpret_cast<const float4*>(&Vs[k2][tc*4]);
            #pragma unroll
            for (int i=0;i<4;i++) {
                #pragma unroll
                for (int j=0;j<4;j++) acc[i][j] += ra[i]*rb[j];
            }
        }
        __syncthreads();
    }
    int b = z >> 4, hh = z & 15;
    #pragma unroll
    for (int i=0;i<4;i++) {
        #pragma unroll
        for (int j=0;j<4;j++)
            g_att[(size_t)(b*SS + row0 + tr*4 + i)*DM + hh*HD + tc*4 + j] = acc[i][j];
    }
}

// out = LayerNorm(res + x) * g + b   (one block per row)
__global__ __launch_bounds__(256) void k_lnadd(const float* __restrict__ res,
        const float* __restrict__ x, const float* __restrict__ g,
        const float* __restrict__ b, float* __restrict__ out) {
    int row = blockIdx.x;
    const float* rp = res + (size_t)row*DM;
    const float* xp = x   + (size_t)row*DM;
    __shared__ float buf[DM];
    __shared__ float red[8];
    int tid = threadIdx.x;
    float s = 0.f;
    for (int d = tid; d < DM; d += 256) { float v = rp[d]+xp[d]; buf[d]=v; s += v; }
    for (int o=16;o;o>>=1) s += __shfl_xor_sync(0xffffffffu, s, o);
    if ((tid&31)==0) red[tid>>5] = s;
    __syncthreads();
    s = red[0];
    #pragma unroll
    for (int i=1;i<8;i++) s += red[i];
    float mu = s * (1.f/DM);
    float vs = 0.f;
    for (int d = tid; d < DM; d += 256) { float v = buf[d]-mu; vs += v*v; }
    __syncthreads();
    for (int o=16;o;o>>=1) vs += __shfl_xor_sync(0xffffffffu, vs, o);
    if ((tid&31)==0) red[tid>>5] = vs;
    __syncthreads();
    vs = red[0];
    #pragma unroll
    for (int i=1;i<8;i++) vs += red[i];
    float inv = rsqrtf(vs * (1.f/DM) + 1e-5f);
    for (int d = tid; d < DM; d += 256)
        out[(size_t)row*DM + d] = (buf[d]-mu)*inv*g[d] + b[d];
}

__global__ __launch_bounds__(256) void k_select() {
    int idx = blockIdx.x*256 + threadIdx.x;
    if (idx < MM*DM) {
        int m = idx >> 10;
        if (!g_skip[m]) g_h[idx] = g_ht[idx];
    }
}

__global__ void k_finalize(float* out, int base) {
    float sk = (float)g_cnt[0], fw = (float)g_cnt[1], rc = (float)g_cnt[2];
    float total = (float)(MM * NL);
    out[base+0] = (fw + rc) / (float)MM;   // effective_depth = mean token depth
    out[base+1] = sk / total;
    out[base+2] = fw / total;
    out[base+3] = rc / total;
}

// ---------------- host driver ----------------
extern "C" void kernel_launch(void* const* d_in, const int* in_sizes, int n_in,
                              void* d_out, int out_size) {
    const int*   x    = (const int*)  d_in[0];
    const float* emb  = (const float*)d_in[1];
    const float* Wq   = (const float*)d_in[2],  *bq   = (const float*)d_in[3];
    const float* Wk   = (const float*)d_in[4],  *bk   = (const float*)d_in[5];
    const float* Wv   = (const float*)d_in[6],  *bv   = (const float*)d_in[7];
    const float* Wo   = (const float*)d_in[8],  *bo   = (const float*)d_in[9];
    const float* ln1g = (const float*)d_in[10], *ln1b = (const float*)d_in[11];
    const float* Wf1  = (const float*)d_in[12], *bf1  = (const float*)d_in[13];
    const float* Wf2  = (const float*)d_in[14], *bf2  = (const float*)d_in[15];
    const float* ln2g = (const float*)d_in[16], *ln2b = (const float*)d_in[17];
    const float* rW1  = (const float*)d_in[18], *rb1  = (const float*)d_in[19];
    const float* rW2  = (const float*)d_in[20], *rb2  = (const float*)d_in[21];
    const float* Wout = (const float*)d_in[22], *bout = (const float*)d_in[23];
    float* out = (float*)d_out;

    float *h, *h1, *ht, *q, *k, *v, *att, *ff, *t2;
    cudaGetSymbolAddress((void**)&h,   g_h);
    cudaGetSymbolAddress((void**)&h1,  g_h1);
    cudaGetSymbolAddress((void**)&ht,  g_ht);
    cudaGetSymbolAddress((void**)&q,   g_q);
    cudaGetSymbolAddress((void**)&k,   g_k);
    cudaGetSymbolAddress((void**)&v,   g_v);
    cudaGetSymbolAddress((void**)&att, g_att);
    cudaGetSymbolAddress((void**)&ff,  g_ff);
    cudaGetSymbolAddress((void**)&t2,  g_t2);

    k_reset<<<1,1>>>();
    k_embed<<<MM,256>>>(x, emb);

    dim3 gqkv(DM/128, MM/128);       // 8 x 16
    dim3 gff1(FFD/128, MM/128);      // 32 x 16
    dim3 gsc(16, 16, NZ);
    dim3 gpv(16, 1, NZ);

    for (int i = 0; i < NL; i++) {
        k_router<<<MM,128>>>(h, rW1 + (size_t)i*DM*RH, rb1 + (size_t)i*RH,
                                rW2 + (size_t)i*RH*3,  rb2 + (size_t)i*3);
        k_sgemm<1><<<gqkv,256>>>(h, Wq, bq, q, MM, DM, DM);
        k_sgemm<1><<<gqkv,256>>>(h, Wk, bk, k, MM, DM, DM);
        k_sgemm<1><<<gqkv,256>>>(h, Wv, bv, v, MM, DM, DM);
        k_scores<<<gsc,256>>>();
        k_softmax<<<NZ*SS,256>>>();
        k_pv<<<gpv,256>>>();
        k_sgemm<0><<<gqkv,256>>>(att, Wo, bo, t2, MM, DM, DM);
        k_lnadd<<<MM,256>>>(h, t2, ln1g, ln1b, h1);
        k_sgemm<2><<<gff1,256>>>(h1, Wf1, bf1, ff, MM, FFD, DM);
        k_sgemm<0><<<gqkv,256>>>(ff, Wf2, bf2, t2, MM, DM, FFD);
        k_lnadd<<<MM,256>>>(h1, t2, ln2g, ln2b, ht);
        k_select<<<(MM*DM + 255)/256, 256>>>();
    }
    k_sgemm<0><<<dim3(32000/128, MM/128),256>>>(h, Wout, bout, out, MM, 32000, DM);
    k_finalize<<<1,1>>>(out, out_size - 4);
}

// round 6
// speedup vs baseline: 1.3726x; 1.3726x over previous
#include <cuda_runtime.h>
#include <math.h>

#define BB 2
#define SS 1024
#define DM 1024
#define NH 16
#define HD 64
#define FFD 4096
#define NL 12
#define RH 128
#define MM (BB*SS)    /* 2048 rows */
#define NZ (BB*NH)    /* 32 (b,h) batches */

// ---------------- scratch (device globals: allocation-free contract) ----------------
__device__ float g_h  [MM*DM];
__device__ float g_h1 [MM*DM];
__device__ float g_ht [MM*DM];
__device__ float g_q  [MM*DM];
__device__ float g_k  [MM*DM];
__device__ float g_v  [MM*DM];
__device__ float g_att[MM*DM];
__device__ float g_ff [MM*FFD];
__device__ float g_t2 [MM*DM];
__device__ float g_rh [MM*RH];
__device__ float g_scores[(size_t)NZ*SS*SS];   // 128 MB
__device__ int   g_skip[MM];
__device__ int   g_cnt[3];

// ---------------- small kernels ----------------
__global__ void k_reset() { g_cnt[0]=0; g_cnt[1]=0; g_cnt[2]=0; }

__global__ __launch_bounds__(256) void k_embed(const int* __restrict__ x,
                                               const float* __restrict__ emb) {
    int row = blockIdx.x;
    int tok = x[row];
    int s   = row & (SS-1);
    const float* e = emb + (size_t)tok * DM;
    for (int d = threadIdx.x; d < DM; d += 256) {
        int p = d >> 1;
        float freq = expf((float)(2*p) * (-9.210340371976184f / 1024.f));
        float ang  = (float)s * freq;
        float pe   = (d & 1) ? cosf(ang) : sinf(ang);
        g_h[row*DM + d] = e[d] * 32.f + pe;   // sqrt(1024) = 32
    }
}

// =====================================================================
// Tuned fp32 GEMM: C[MxN] = A[MxK] @ B[KxN] + bias
// BM=128, BN=64, BK=16, 256 threads, 8x4 per thread, double-buffered smem.
// MODE 0: plain store   MODE 2: relu
// =====================================================================
#define GEMM_BODY(BUFI)                                                          \
    {                                                                            \
        _Pragma("unroll")                                                        \
        for (int k2 = 0; k2 < 16; k2++) {                                        \
            float ra[8], rb[4];                                                  \
            *reinterpret_cast<float4*>(ra  ) = *reinterpret_cast<const float4*>(&As[BUFI][k2][tr*8  ]); \
            *reinterpret_cast<float4*>(ra+4) = *reinterpret_cast<const float4*>(&As[BUFI][k2][tr*8+4]); \
            *reinterpret_cast<float4*>(rb  ) = *reinterpret_cast<const float4*>(&Bs[BUFI][k2][tc*4  ]); \
            _Pragma("unroll")                                                    \
            for (int i = 0; i < 8; i++) {                                        \
                _Pragma("unroll")                                                \
                for (int j = 0; j < 4; j++) acc[i][j] += ra[i]*rb[j];            \
            }                                                                    \
        }                                                                        \
    }

#define GEMM_STORE_SMEM(BUFI)                                                    \
    {                                                                            \
        As[BUFI][aCol+0][aRow   ]=a0.x; As[BUFI][aCol+1][aRow   ]=a0.y;          \
        As[BUFI][aCol+2][aRow   ]=a0.z; As[BUFI][aCol+3][aRow   ]=a0.w;          \
        As[BUFI][aCol+0][aRow+64]=a1.x; As[BUFI][aCol+1][aRow+64]=a1.y;          \
        As[BUFI][aCol+2][aRow+64]=a1.z; As[BUFI][aCol+3][aRow+64]=a1.w;          \
        *reinterpret_cast<float4*>(&Bs[BUFI][bRow][bCol]) = b0;                  \
    }

template<int MODE>
__global__ __launch_bounds__(256, 2) void k_gemm(const float* __restrict__ A,
        const float* __restrict__ B, const float* __restrict__ bias,
        float* __restrict__ C, int M, int N, int K) {
    __shared__ float As[2][16][128];
    __shared__ float Bs[2][16][64];
    int tid = threadIdx.x;
    int tr = tid >> 4, tc = tid & 15;
    int aRow = tid >> 2, aCol = (tid & 3) << 2;
    int bRow = tid >> 4, bCol = (tid & 15) << 2;
    const float* Ab = A + (size_t)(blockIdx.y * 128) * K;
    const float* Bb = B + (size_t)blockIdx.x * 64;

    float4 a0 = *reinterpret_cast<const float4*>(Ab + (size_t)aRow*K + aCol);
    float4 a1 = *reinterpret_cast<const float4*>(Ab + (size_t)(aRow+64)*K + aCol);
    float4 b0 = *reinterpret_cast<const float4*>(Bb + (size_t)bRow*N + bCol);
    GEMM_STORE_SMEM(0)
    __syncthreads();

    float acc[8][4] = {};
    int buf = 0;
    for (int kk = 16; kk < K; kk += 16) {
        a0 = *reinterpret_cast<const float4*>(Ab + (size_t)aRow*K + kk + aCol);
        a1 = *reinterpret_cast<const float4*>(Ab + (size_t)(aRow+64)*K + kk + aCol);
        b0 = *reinterpret_cast<const float4*>(Bb + (size_t)(kk+bRow)*N + bCol);
        GEMM_BODY(buf)
        GEMM_STORE_SMEM(buf^1)
        __syncthreads();
        buf ^= 1;
    }
    GEMM_BODY(buf)

    int m0 = blockIdx.y*128 + tr*8;
    int n0 = blockIdx.x*64  + tc*4;
    #pragma unroll
    for (int i = 0; i < 8; i++) {
        #pragma unroll
        for (int j = 0; j < 4; j++) {
            float val = acc[i][j] + bias[n0+j];
            if (MODE == 2) val = fmaxf(val, 0.f);
            C[(size_t)(m0+i)*N + n0 + j] = val;
        }
    }
}

// fused QKV: grid.x in [0,48): sel = bx>>4 chooses W/bias/output, head = bx&15.
__global__ __launch_bounds__(256, 2) void k_gemm_qkv(const float* __restrict__ A,
        const float* __restrict__ Wq, const float* __restrict__ Wk, const float* __restrict__ Wv,
        const float* __restrict__ bq, const float* __restrict__ bk, const float* __restrict__ bv) {
    const int N = DM, K = DM;
    int sel = blockIdx.x >> 4;
    int hh  = blockIdx.x & 15;
    const float* B    = (sel==0) ? Wq : (sel==1) ? Wk : Wv;
    const float* bias = (sel==0) ? bq : (sel==1) ? bk : bv;
    float* C          = (sel==0) ? g_q : (sel==1) ? g_k : g_v;

    __shared__ float As[2][16][128];
    __shared__ float Bs[2][16][64];
    int tid = threadIdx.x;
    int tr = tid >> 4, tc = tid & 15;
    int aRow = tid >> 2, aCol = (tid & 3) << 2;
    int bRow = tid >> 4, bCol = (tid & 15) << 2;
    const float* Ab = A + (size_t)(blockIdx.y * 128) * K;
    const float* Bb = B + (size_t)hh * 64;

    float4 a0 = *reinterpret_cast<const float4*>(Ab + (size_t)aRow*K + aCol);
    float4 a1 = *reinterpret_cast<const float4*>(Ab + (size_t)(aRow+64)*K + aCol);
    float4 b0 = *reinterpret_cast<const float4*>(Bb + (size_t)bRow*N + bCol);
    GEMM_STORE_SMEM(0)
    __syncthreads();

    float acc[8][4] = {};
    int buf = 0;
    for (int kk = 16; kk < K; kk += 16) {
        a0 = *reinterpret_cast<const float4*>(Ab + (size_t)aRow*K + kk + aCol);
        a1 = *reinterpret_cast<const float4*>(Ab + (size_t)(aRow+64)*K + kk + aCol);
        b0 = *reinterpret_cast<const float4*>(Bb + (size_t)(kk+bRow)*N + bCol);
        GEMM_BODY(buf)
        GEMM_STORE_SMEM(buf^1)
        __syncthreads();
        buf ^= 1;
    }
    GEMM_BODY(buf)

    int m0 = blockIdx.y*128 + tr*8;
    int d0 = tc*4;   // column within this head (0..63)
    #pragma unroll
    for (int i = 0; i < 8; i++) {
        int m = m0 + i;
        int b = m >> 10, s = m & 1023;
        float* crow = C + (size_t)(((b*NH + hh)*SS) + s)*HD + d0;
        #pragma unroll
        for (int j = 0; j < 4; j++)
            crow[j] = acc[i][j] + bias[hh*64 + d0 + j];
    }
}

// router tail: logits = rh @ W2 + b2 (3 cols), argmax. one warp per row.
__global__ __launch_bounds__(256) void k_argmax(const float* __restrict__ W2,
                                                const float* __restrict__ b2) {
    int row  = blockIdx.x*8 + (threadIdx.x >> 5);
    int lane = threadIdx.x & 31;
    const float* r = g_rh + (size_t)row*RH;
    float s0 = 0.f, s1 = 0.f, s2 = 0.f;
    #pragma unroll
    for (int j = lane; j < RH; j += 32) {
        float v = r[j];
        s0 += v*W2[j*3+0]; s1 += v*W2[j*3+1]; s2 += v*W2[j*3+2];
    }
    #pragma unroll
    for (int o = 16; o; o >>= 1) {
        s0 += __shfl_xor_sync(0xffffffffu, s0, o);
        s1 += __shfl_xor_sync(0xffffffffu, s1, o);
        s2 += __shfl_xor_sync(0xffffffffu, s2, o);
    }
    if (lane == 0) {
        s0 += b2[0]; s1 += b2[1]; s2 += b2[2];
        int a = 0; float best = s0;
        if (s1 > best) { best = s1; a = 1; }
        if (s2 > best) { a = 2; }
        g_skip[row] = (a == 0);
        atomicAdd(&g_cnt[a], 1);
    }
}

// ---------------- attention: scores = q@k^T / 8 (causal blocks only) ----------------
__global__ __launch_bounds__(256) void k_scores() {
    int z = blockIdx.z;
    int row0 = blockIdx.y*64, col0 = blockIdx.x*64;
    if (col0 > row0 + 63) return;       // fully above diagonal: never read
    const float* Q  = g_q + (size_t)z*SS*HD;
    const float* Kp = g_k + (size_t)z*SS*HD;
    float* out = g_scores + (size_t)z*SS*SS;
    __shared__ float Qs[16][64];
    __shared__ float Ks[16][64];
    int tid = threadIdx.x;
    int lr = tid >> 2, lc = (tid & 3) << 2;
    int tr = tid >> 4, tc = tid & 15;
    float acc[4][4] = {};
    for (int kk = 0; kk < HD; kk += 16) {
        float4 q4 = *reinterpret_cast<const float4*>(Q  + (size_t)(row0+lr)*HD + kk + lc);
        Qs[lc+0][lr]=q4.x; Qs[lc+1][lr]=q4.y; Qs[lc+2][lr]=q4.z; Qs[lc+3][lr]=q4.w;
        float4 k4 = *reinterpret_cast<const float4*>(Kp + (size_t)(col0+lr)*HD + kk + lc);
        Ks[lc+0][lr]=k4.x; Ks[lc+1][lr]=k4.y; Ks[lc+2][lr]=k4.z; Ks[lc+3][lr]=k4.w;
        __syncthreads();
        #pragma unroll
        for (int k2 = 0; k2 < 16; k2++) {
            float ra[4], rb[4];
            *reinterpret_cast<float4*>(ra) = *reinterpret_cast<const float4*>(&Qs[k2][tr*4]);
            *reinterpret_cast<float4*>(rb) = *reinterpret_cast<const float4*>(&Ks[k2][tc*4]);
            #pragma unroll
            for (int i=0;i<4;i++) {
                #pragma unroll
                for (int j=0;j<4;j++) acc[i][j] += ra[i]*rb[j];
            }
        }
        __syncthreads();
    }
    #pragma unroll
    for (int i=0;i<4;i++) {
        #pragma unroll
        for (int j=0;j<4;j++)
            out[(size_t)(row0 + tr*4 + i)*SS + col0 + tc*4 + j] = acc[i][j]*0.125f;
    }
}

// row softmax, causal: only k<=q valid; zero the tail so PV can run dense
__global__ __launch_bounds__(256) void k_softmax() {
    int r = blockIdx.x;
    int L = (r & (SS-1)) + 1;
    float* row = g_scores + (size_t)r*SS;
    __shared__ float buf[SS];
    __shared__ float red[8];
    int tid = threadIdx.x;
    float mx = -INFINITY;
    for (int c = tid; c < L; c += 256) { float v = row[c]; buf[c] = v; mx = fmaxf(mx, v); }
    for (int o=16;o;o>>=1) mx = fmaxf(mx, __shfl_xor_sync(0xffffffffu, mx, o));
    if ((tid&31)==0) red[tid>>5] = mx;
    __syncthreads();
    mx = red[0];
    #pragma unroll
    for (int i=1;i<8;i++) mx = fmaxf(mx, red[i]);
    float s = 0.f;
    for (int c = tid; c < L; c += 256) { float e = expf(buf[c]-mx); buf[c]=e; s += e; }
    __syncthreads();
    for (int o=16;o;o>>=1) s += __shfl_xor_sync(0xffffffffu, s, o);
    if ((tid&31)==0) red[tid>>5] = s;
    __syncthreads();
    s = red[0];
    #pragma unroll
    for (int i=1;i<8;i++) s += red[i];
    for (int c = tid; c < SS; c += 256) row[c] = (c < L) ? buf[c]/s : 0.f;
}

// attn @ v  -> g_att in [B,S,D] layout.  K loop truncated: probs zero past row0+63.
__global__ __launch_bounds__(256) void k_pv() {
    int z = blockIdx.z;
    int row0 = blockIdx.x*64;
    const float* P = g_scores + (size_t)z*SS*SS;
    const float* V = g_v      + (size_t)z*SS*HD;
    __shared__ float Ps[16][64];
    __shared__ float Vs[16][64];
    int tid = threadIdx.x;
    int pr = tid >> 2, pc = (tid & 3) << 2;
    int vr = tid >> 4, vc = (tid & 15) << 2;
    int tr = tid >> 4, tc = tid & 15;
    float acc[4][4] = {};
    int kmax = row0 + 64;
    for (int kk = 0; kk < kmax; kk += 16) {
        float4 p4 = *reinterpret_cast<const float4*>(P + (size_t)(row0+pr)*SS + kk + pc);
        Ps[pc+0][pr]=p4.x; Ps[pc+1][pr]=p4.y; Ps[pc+2][pr]=p4.z; Ps[pc+3][pr]=p4.w;
        float4 v4 = *reinterpret_cast<const float4*>(V + (size_t)(kk+vr)*HD + vc);
        *reinterpret_cast<float4*>(&Vs[vr][vc]) = v4;
        __syncthreads();
        #pragma unroll
        for (int k2 = 0; k2 < 16; k2++) {
            float ra[4], rb[4];
            *reinterpret_cast<float4*>(ra) = *reinterpret_cast<const float4*>(&Ps[k2][tr*4]);
            *reinterpret_cast<float4*>(rb) = *reinterpret_cast<const float4*>(&Vs[k2][tc*4]);
            #pragma unroll
            for (int i=0;i<4;i++) {
                #pragma unroll
                for (int j=0;j<4;j++) acc[i][j] += ra[i]*rb[j];
            }
        }
        __syncthreads();
    }
    int b = z >> 4, hh = z & 15;
    #pragma unroll
    for (int i=0;i<4;i++) {
        #pragma unroll
        for (int j=0;j<4;j++)
            g_att[(size_t)(b*SS + row0 + tr*4 + i)*DM + hh*HD + tc*4 + j] = acc[i][j];
    }
}

// out = LayerNorm(res + x) * g + b   (one block per row)
__global__ __launch_bounds__(256) void k_lnadd(const float* __restrict__ res,
        const float* __restrict__ x, const float* __restrict__ g,
        const float* __restrict__ b, float* __restrict__ out) {
    int row = blockIdx.x;
    const float* rp = res + (size_t)row*DM;
    const float* xp = x   + (size_t)row*DM;
    __shared__ float buf[DM];
    __shared__ float red[8];
    int tid = threadIdx.x;
    float s = 0.f;
    for (int d = tid; d < DM; d += 256) { float v = rp[d]+xp[d]; buf[d]=v; s += v; }
    for (int o=16;o;o>>=1) s += __shfl_xor_sync(0xffffffffu, s, o);
    if ((tid&31)==0) red[tid>>5] = s;
    __syncthreads();
    s = red[0];
    #pragma unroll
    for (int i=1;i<8;i++) s += red[i];
    float mu = s * (1.f/DM);
    float vs = 0.f;
    for (int d = tid; d < DM; d += 256) { float v = buf[d]-mu; vs += v*v; }
    __syncthreads();
    for (int o=16;o;o>>=1) vs += __shfl_xor_sync(0xffffffffu, vs, o);
    if ((tid&31)==0) red[tid>>5] = vs;
    __syncthreads();
    vs = red[0];
    #pragma unroll
    for (int i=1;i<8;i++) vs += red[i];
    float inv = rsqrtf(vs * (1.f/DM) + 1e-5f);
    for (int d = tid; d < DM; d += 256)
        out[(size_t)row*DM + d] = (buf[d]-mu)*inv*g[d] + b[d];
}

__global__ __launch_bounds__(256) void k_select() {
    int idx = blockIdx.x*256 + threadIdx.x;
    if (idx < MM*DM) {
        int m = idx >> 10;
        if (!g_skip[m]) g_h[idx] = g_ht[idx];
    }
}

__global__ void k_finalize(float* out, int base) {
    float sk = (float)g_cnt[0], fw = (float)g_cnt[1], rc = (float)g_cnt[2];
    float total = (float)(MM * NL);
    out[base+0] = (fw + rc) / (float)MM;   // effective_depth = mean token depth
    out[base+1] = sk / total;
    out[base+2] = fw / total;
    out[base+3] = rc / total;
}

// ---------------- host driver ----------------
extern "C" void kernel_launch(void* const* d_in, const int* in_sizes, int n_in,
                              void* d_out, int out_size) {
    const int*   x    = (const int*)  d_in[0];
    const float* emb  = (const float*)d_in[1];
    const float* Wq   = (const float*)d_in[2],  *bq   = (const float*)d_in[3];
    const float* Wk   = (const float*)d_in[4],  *bk   = (const float*)d_in[5];
    const float* Wv   = (const float*)d_in[6],  *bv   = (const float*)d_in[7];
    const float* Wo   = (const float*)d_in[8],  *bo   = (const float*)d_in[9];
    const float* ln1g = (const float*)d_in[10], *ln1b = (const float*)d_in[11];
    const float* Wf1  = (const float*)d_in[12], *bf1  = (const float*)d_in[13];
    const float* Wf2  = (const float*)d_in[14], *bf2  = (const float*)d_in[15];
    const float* ln2g = (const float*)d_in[16], *ln2b = (const float*)d_in[17];
    const float* rW1  = (const float*)d_in[18], *rb1  = (const float*)d_in[19];
    const float* rW2  = (const float*)d_in[20], *rb2  = (const float*)d_in[21];
    const float* Wout = (const float*)d_in[22], *bout = (const float*)d_in[23];
    float* out = (float*)d_out;

    float *h, *h1, *ht, *att, *ff, *t2, *rh;
    cudaGetSymbolAddress((void**)&h,   g_h);
    cudaGetSymbolAddress((void**)&h1,  g_h1);
    cudaGetSymbolAddress((void**)&ht,  g_ht);
    cudaGetSymbolAddress((void**)&att, g_att);
    cudaGetSymbolAddress((void**)&ff,  g_ff);
    cudaGetSymbolAddress((void**)&t2,  g_t2);
    cudaGetSymbolAddress((void**)&rh,  g_rh);

    k_reset<<<1,1>>>();
    k_embed<<<MM,256>>>(x, emb);

    dim3 gdd (DM/64,  MM/128);    // 16 x 16  (D x D GEMMs)
    dim3 gqkv(48,     MM/128);    // fused QKV
    dim3 gff1(FFD/64, MM/128);    // 64 x 16
    dim3 grt (RH/64,  MM/128);    // 2 x 16   (router hidden)
    dim3 gsc (16, 16, NZ);
    dim3 gpv (16, 1,  NZ);

    for (int i = 0; i < NL; i++) {
        k_gemm<2><<<grt,256>>>(h, rW1 + (size_t)i*DM*RH, rb1 + (size_t)i*RH, rh, MM, RH, DM);
        k_argmax<<<MM/8,256>>>(rW2 + (size_t)i*RH*3, rb2 + (size_t)i*3);
        k_gemm_qkv<<<gqkv,256>>>(h, Wq, Wk, Wv, bq, bk, bv);
        k_scores<<<gsc,256>>>();
        k_softmax<<<NZ*SS,256>>>();
        k_pv<<<gpv,256>>>();
        k_gemm<0><<<gdd,256>>>(att, Wo, bo, t2, MM, DM, DM);
        k_lnadd<<<MM,256>>>(h, t2, ln1g, ln1b, h1);
        k_gemm<2><<<gff1,256>>>(h1, Wf1, bf1, ff, MM, FFD, DM);
        k_gemm<0><<<gdd,256>>>(ff, Wf2, bf2, t2, MM, DM, FFD);
        k_lnadd<<<MM,256>>>(h1, t2, ln2g, ln2b, ht);
        k_select<<<(MM*DM + 255)/256, 256>>>();
    }
    k_gemm<0><<<dim3(32000/64, MM/128),256>>>(h, Wout, bout, out, MM, 32000, DM);
    k_finalize<<<1,1>>>(out, out_size - 4);
}

// round 7
// speedup vs baseline: 1.4852x; 1.0821x over previous
#include <cuda_runtime.h>
#include <math.h>

#define BB 2
#define SS 1024
#define DM 1024
#define NH 16
#define HD 64
#define FFD 4096
#define NL 12
#define RH 128
#define MM (BB*SS)    /* 2048 rows */
#define NZ (BB*NH)    /* 32 (b,h) batches */

// ---------------- scratch (device globals: allocation-free contract) ----------------
__device__ float g_h  [MM*DM];
__device__ float g_h1 [MM*DM];
__device__ float g_q  [MM*DM];
__device__ float g_k  [MM*DM];
__device__ float g_v  [MM*DM];
__device__ float g_att[MM*DM];
__device__ float g_ff [MM*FFD];
__device__ float g_t2 [MM*DM];
__device__ float g_rh [MM*RH];
__device__ float g_scores[(size_t)NZ*SS*SS];   // 128 MB
__device__ int   g_skip[MM];
__device__ int   g_cnt[3];

// ---------------- small kernels ----------------
__global__ void k_reset() { g_cnt[0]=0; g_cnt[1]=0; g_cnt[2]=0; }

__global__ __launch_bounds__(256) void k_embed(const int* __restrict__ x,
                                               const float* __restrict__ emb) {
    int row = blockIdx.x;
    int tok = x[row];
    int s   = row & (SS-1);
    const float* e = emb + (size_t)tok * DM;
    for (int d = threadIdx.x; d < DM; d += 256) {
        int p = d >> 1;
        float freq = expf((float)(2*p) * (-9.210340371976184f / 1024.f));
        float ang  = (float)s * freq;
        float pe   = (d & 1) ? cosf(ang) : sinf(ang);
        g_h[row*DM + d] = e[d] * 32.f + pe;   // sqrt(1024) = 32
    }
}

// =====================================================================
// 3xTF32 tensor-core GEMM: C[MxN] = A[MxK] @ B[KxN] + bias  (fp32-accurate)
// BM=128, BN=64, BK=16, 256 threads (8 warps, warp tile 32x32),
// mma.sync.m16n8k8.tf32 with hi/lo split: hi*hi + lo*hi + hi*lo.
// smem strides 136/72 (== 8 mod 32) -> conflict-free fragment gathers.
// =====================================================================
__device__ __forceinline__ unsigned f2tf(float f) {
    unsigned r; asm("cvt.rna.tf32.f32 %0, %1;" : "=r"(r) : "f"(f)); return r;
}
__device__ __forceinline__ void mma_tf32(float* d, const unsigned* a, const unsigned* b) {
    asm("mma.sync.aligned.m16n8k8.row.col.f32.tf32.tf32.f32 "
        "{%0,%1,%2,%3},{%4,%5,%6,%7},{%8,%9},{%0,%1,%2,%3};"
        : "+f"(d[0]), "+f"(d[1]), "+f"(d[2]), "+f"(d[3])
        : "r"(a[0]), "r"(a[1]), "r"(a[2]), "r"(a[3]), "r"(b[0]), "r"(b[1]));
}

#define LDG_TILES(KK)                                                              \
    a0 = *reinterpret_cast<const float4*>(Ab + (size_t)aRow*K + (KK) + aCol);      \
    a1 = *reinterpret_cast<const float4*>(Ab + (size_t)(aRow+64)*K + (KK) + aCol); \
    b0 = *reinterpret_cast<const float4*>(Bb + (size_t)((KK)+bRow)*N + bCol);

#define STS_TILES(BUFI)                                                            \
    As[BUFI][(aCol+0)*136+aRow   ]=a0.x; As[BUFI][(aCol+1)*136+aRow   ]=a0.y;      \
    As[BUFI][(aCol+2)*136+aRow   ]=a0.z; As[BUFI][(aCol+3)*136+aRow   ]=a0.w;      \
    As[BUFI][(aCol+0)*136+aRow+64]=a1.x; As[BUFI][(aCol+1)*136+aRow+64]=a1.y;      \
    As[BUFI][(aCol+2)*136+aRow+64]=a1.z; As[BUFI][(aCol+3)*136+aRow+64]=a1.w;      \
    *reinterpret_cast<float4*>(&Bs[BUFI][bRow*72+bCol]) = b0;

#define MMA_STAGE(BUFI)                                                            \
  {                                                                                \
    _Pragma("unroll")                                                              \
    for (int kh = 0; kh < 2; kh++) {                                               \
      const int k0 = kh*8;                                                         \
      unsigned ahi[2][4], alo[2][4];                                               \
      _Pragma("unroll")                                                            \
      for (int mt = 0; mt < 2; mt++) {                                             \
        _Pragma("unroll")                                                          \
        for (int i = 0; i < 4; i++) {                                              \
          int rr = wm + mt*16 + (lane>>2) + ((i&1)<<3);                            \
          int kc = k0 + (lane&3) + ((i>>1)<<2);                                    \
          float v = As[BUFI][kc*136 + rr];                                         \
          unsigned hv = f2tf(v);                                                   \
          ahi[mt][i] = hv;                                                         \
          alo[mt][i] = f2tf(v - __uint_as_float(hv));                              \
        }                                                                          \
      }                                                                            \
      _Pragma("unroll")                                                            \
      for (int nt = 0; nt < 4; nt++) {                                             \
        unsigned bhi[2], blo[2];                                                   \
        _Pragma("unroll")                                                          \
        for (int i = 0; i < 2; i++) {                                              \
          int kc = k0 + (lane&3) + (i<<2);                                         \
          float v = Bs[BUFI][kc*72 + wn + nt*8 + (lane>>2)];                       \
          unsigned hv = f2tf(v);                                                   \
          bhi[i] = hv;                                                             \
          blo[i] = f2tf(v - __uint_as_float(hv));                                  \
        }                                                                          \
        _Pragma("unroll")                                                          \
        for (int mt = 0; mt < 2; mt++) {                                           \
          mma_tf32(acc[mt][nt], ahi[mt], bhi);                                     \
          mma_tf32(acc[mt][nt], alo[mt], bhi);                                     \
          mma_tf32(acc[mt][nt], ahi[mt], blo);                                     \
        }                                                                          \
      }                                                                            \
    }                                                                              \
  }

#define MMA_MAINLOOP()                                                             \
    float4 a0, a1, b0;                                                             \
    LDG_TILES(0)                                                                   \
    STS_TILES(0)                                                                   \
    __syncthreads();                                                               \
    int buf = 0;                                                                   \
    for (int kk = 16; kk < K; kk += 16) {                                          \
        LDG_TILES(kk)                                                              \
        MMA_STAGE(buf)                                                             \
        STS_TILES(buf^1)                                                           \
        __syncthreads();                                                           \
        buf ^= 1;                                                                  \
    }                                                                              \
    MMA_STAGE(buf)

// MODE 0: plain store   MODE 2: relu
template<int MODE>
__global__ __launch_bounds__(256, 2) void k_gemm(const float* __restrict__ A,
        const float* __restrict__ B, const float* __restrict__ bias,
        float* __restrict__ C, int M, int N, int K) {
    __shared__ float As[2][16*136];
    __shared__ float Bs[2][16*72];
    int tid = threadIdx.x, lane = tid & 31, wid = tid >> 5;
    int wm = (wid & 3) * 32, wn = (wid >> 2) * 32;
    int aRow = tid >> 2, aCol = (tid & 3) << 2;
    int bRow = tid >> 4, bCol = (tid & 15) << 2;
    const float* Ab = A + (size_t)(blockIdx.y * 128) * K;
    const float* Bb = B + (size_t)blockIdx.x * 64;
    float acc[2][4][4] = {};

    MMA_MAINLOOP()

    int mBase = blockIdx.y*128 + wm + (lane>>2);
    int nBase = blockIdx.x*64  + wn + ((lane&3)<<1);
    #pragma unroll
    for (int mt = 0; mt < 2; mt++) {
        #pragma unroll
        for (int nt = 0; nt < 4; nt++) {
            int r = mBase + mt*16;
            int c = nBase + nt*8;
            float v0 = acc[mt][nt][0] + bias[c];
            float v1 = acc[mt][nt][1] + bias[c+1];
            float v2 = acc[mt][nt][2] + bias[c];
            float v3 = acc[mt][nt][3] + bias[c+1];
            if (MODE == 2) {
                v0 = fmaxf(v0,0.f); v1 = fmaxf(v1,0.f);
                v2 = fmaxf(v2,0.f); v3 = fmaxf(v3,0.f);
            }
            float* p  = C + (size_t)r*N + c;
            float* p2 = p + (size_t)8*N;
            p [0] = v0; p [1] = v1;
            p2[0] = v2; p2[1] = v3;
        }
    }
}

// fused QKV: grid.x in [0,48): sel = bx>>4 chooses W/bias/output, head = bx&15.
__global__ __launch_bounds__(256, 2) void k_gemm_qkv(const float* __restrict__ A,
        const float* __restrict__ Wq, const float* __restrict__ Wk, const float* __restrict__ Wv,
        const float* __restrict__ bq, const float* __restrict__ bk, const float* __restrict__ bv) {
    const int N = DM, K = DM;
    int sel = blockIdx.x >> 4;
    int hh  = blockIdx.x & 15;
    const float* B    = (sel==0) ? Wq : (sel==1) ? Wk : Wv;
    const float* bias = (sel==0) ? bq : (sel==1) ? bk : bv;
    float* C          = (sel==0) ? g_q : (sel==1) ? g_k : g_v;

    __shared__ float As[2][16*136];
    __shared__ float Bs[2][16*72];
    int tid = threadIdx.x, lane = tid & 31, wid = tid >> 5;
    int wm = (wid & 3) * 32, wn = (wid >> 2) * 32;
    int aRow = tid >> 2, aCol = (tid & 3) << 2;
    int bRow = tid >> 4, bCol = (tid & 15) << 2;
    const float* Ab = A + (size_t)(blockIdx.y * 128) * K;
    const float* Bb = B + (size_t)hh * 64;
    float acc[2][4][4] = {};

    MMA_MAINLOOP()

    int mBase = blockIdx.y*128 + wm + (lane>>2);
    int d0    = wn + ((lane&3)<<1);     // column within head (0..63)
    #pragma unroll
    for (int mt = 0; mt < 2; mt++) {
        #pragma unroll
        for (int nt = 0; nt < 4; nt++) {
            int d = d0 + nt*8;
            float bv0 = bias[hh*64 + d], bv1 = bias[hh*64 + d + 1];
            #pragma unroll
            for (int half = 0; half < 2; half++) {
                int m = mBase + mt*16 + half*8;
                int b = m >> 10, s = m & 1023;
                float* crow = C + (size_t)(((b*NH + hh)*SS) + s)*HD + d;
                crow[0] = acc[mt][nt][half*2+0] + bv0;
                crow[1] = acc[mt][nt][half*2+1] + bv1;
            }
        }
    }
}

// router tail: logits = rh @ W2 + b2 (3 cols), argmax. one warp per row.
__global__ __launch_bounds__(256) void k_argmax(const float* __restrict__ W2,
                                                const float* __restrict__ b2) {
    int row  = blockIdx.x*8 + (threadIdx.x >> 5);
    int lane = threadIdx.x & 31;
    const float* r = g_rh + (size_t)row*RH;
    float s0 = 0.f, s1 = 0.f, s2 = 0.f;
    #pragma unroll
    for (int j = lane; j < RH; j += 32) {
        float v = r[j];
        s0 += v*W2[j*3+0]; s1 += v*W2[j*3+1]; s2 += v*W2[j*3+2];
    }
    #pragma unroll
    for (int o = 16; o; o >>= 1) {
        s0 += __shfl_xor_sync(0xffffffffu, s0, o);
        s1 += __shfl_xor_sync(0xffffffffu, s1, o);
        s2 += __shfl_xor_sync(0xffffffffu, s2, o);
    }
    if (lane == 0) {
        s0 += b2[0]; s1 += b2[1]; s2 += b2[2];
        int a = 0; float best = s0;
        if (s1 > best) { best = s1; a = 1; }
        if (s2 > best) { a = 2; }
        g_skip[row] = (a == 0);
        atomicAdd(&g_cnt[a], 1);
    }
}

// ---------------- attention: scores = q@k^T / 8 (causal blocks only) ----------------
__global__ __launch_bounds__(256) void k_scores() {
    int z = blockIdx.z;
    int row0 = blockIdx.y*64, col0 = blockIdx.x*64;
    if (col0 > row0 + 63) return;       // fully above diagonal: never read
    const float* Q  = g_q + (size_t)z*SS*HD;
    const float* Kp = g_k + (size_t)z*SS*HD;
    float* out = g_scores + (size_t)z*SS*SS;
    __shared__ float Qs[16][64];
    __shared__ float Ks[16][64];
    int tid = threadIdx.x;
    int lr = tid >> 2, lc = (tid & 3) << 2;
    int tr = tid >> 4, tc = tid & 15;
    float acc[4][4] = {};
    for (int kk = 0; kk < HD; kk += 16) {
        float4 q4 = *reinterpret_cast<const float4*>(Q  + (size_t)(row0+lr)*HD + kk + lc);
        Qs[lc+0][lr]=q4.x; Qs[lc+1][lr]=q4.y; Qs[lc+2][lr]=q4.z; Qs[lc+3][lr]=q4.w;
        float4 k4 = *reinterpret_cast<const float4*>(Kp + (size_t)(col0+lr)*HD + kk + lc);
        Ks[lc+0][lr]=k4.x; Ks[lc+1][lr]=k4.y; Ks[lc+2][lr]=k4.z; Ks[lc+3][lr]=k4.w;
        __syncthreads();
        #pragma unroll
        for (int k2 = 0; k2 < 16; k2++) {
            float ra[4], rb[4];
            *reinterpret_cast<float4*>(ra) = *reinterpret_cast<const float4*>(&Qs[k2][tr*4]);
            *reinterpret_cast<float4*>(rb) = *reinterpret_cast<const float4*>(&Ks[k2][tc*4]);
            #pragma unroll
            for (int i=0;i<4;i++) {
                #pragma unroll
                for (int j=0;j<4;j++) acc[i][j] += ra[i]*rb[j];
            }
        }
        __syncthreads();
    }
    #pragma unroll
    for (int i=0;i<4;i++) {
        #pragma unroll
        for (int j=0;j<4;j++)
            out[(size_t)(row0 + tr*4 + i)*SS + col0 + tc*4 + j] = acc[i][j]*0.125f;
    }
}

// row softmax, causal: only k<=q valid; zero the tail so PV can run dense
__global__ __launch_bounds__(256) void k_softmax() {
    int r = blockIdx.x;
    int L = (r & (SS-1)) + 1;
    float* row = g_scores + (size_t)r*SS;
    __shared__ float buf[SS];
    __shared__ float red[8];
    int tid = threadIdx.x;
    float mx = -INFINITY;
    for (int c = tid; c < L; c += 256) { float v = row[c]; buf[c] = v; mx = fmaxf(mx, v); }
    for (int o=16;o;o>>=1) mx = fmaxf(mx, __shfl_xor_sync(0xffffffffu, mx, o));
    if ((tid&31)==0) red[tid>>5] = mx;
    __syncthreads();
    mx = red[0];
    #pragma unroll
    for (int i=1;i<8;i++) mx = fmaxf(mx, red[i]);
    float s = 0.f;
    for (int c = tid; c < L; c += 256) { float e = expf(buf[c]-mx); buf[c]=e; s += e; }
    __syncthreads();
    for (int o=16;o;o>>=1) s += __shfl_xor_sync(0xffffffffu, s, o);
    if ((tid&31)==0) red[tid>>5] = s;
    __syncthreads();
    s = red[0];
    #pragma unroll
    for (int i=1;i<8;i++) s += red[i];
    for (int c = tid; c < SS; c += 256) row[c] = (c < L) ? buf[c]/s : 0.f;
}

// attn @ v  -> g_att in [B,S,D] layout.  K loop truncated: probs zero past row0+63.
__global__ __launch_bounds__(256) void k_pv() {
    int z = blockIdx.z;
    int row0 = blockIdx.x*64;
    const float* P = g_scores + (size_t)z*SS*SS;
    const float* V = g_v      + (size_t)z*SS*HD;
    __shared__ float Ps[16][64];
    __shared__ float Vs[16][64];
    int tid = threadIdx.x;
    int pr = tid >> 2, pc = (tid & 3) << 2;
    int vr = tid >> 4, vc = (tid & 15) << 2;
    int tr = tid >> 4, tc = tid & 15;
    float acc[4][4] = {};
    int kmax = row0 + 64;
    for (int kk = 0; kk < kmax; kk += 16) {
        float4 p4 = *reinterpret_cast<const float4*>(P + (size_t)(row0+pr)*SS + kk + pc);
        Ps[pc+0][pr]=p4.x; Ps[pc+1][pr]=p4.y; Ps[pc+2][pr]=p4.z; Ps[pc+3][pr]=p4.w;
        float4 v4 = *reinterpret_cast<const float4*>(V + (size_t)(kk+vr)*HD + vc);
        *reinterpret_cast<float4*>(&Vs[vr][vc]) = v4;
        __syncthreads();
        #pragma unroll
        for (int k2 = 0; k2 < 16; k2++) {
            float ra[4], rb[4];
            *reinterpret_cast<float4*>(ra) = *reinterpret_cast<const float4*>(&Ps[k2][tr*4]);
            *reinterpret_cast<float4*>(rb) = *reinterpret_cast<const float4*>(&Vs[k2][tc*4]);
            #pragma unroll
            for (int i=0;i<4;i++) {
                #pragma unroll
                for (int j=0;j<4;j++) acc[i][j] += ra[i]*rb[j];
            }
        }
        __syncthreads();
    }
    int b = z >> 4, hh = z & 15;
    #pragma unroll
    for (int i=0;i<4;i++) {
        #pragma unroll
        for (int j=0;j<4;j++)
            g_att[(size_t)(b*SS + row0 + tr*4 + i)*DM + hh*HD + tc*4 + j] = acc[i][j];
    }
}

// out = LayerNorm(res + x) * g + b   (one block per row)
__global__ __launch_bounds__(256) void k_lnadd(const float* __restrict__ res,
        const float* __restrict__ x, const float* __restrict__ g,
        const float* __restrict__ b, float* __restrict__ out) {
    int row = blockIdx.x;
    const float* rp = res + (size_t)row*DM;
    const float* xp = x   + (size_t)row*DM;
    __shared__ float buf[DM];
    __shared__ float red[8];
    int tid = threadIdx.x;
    float s = 0.f;
    for (int d = tid; d < DM; d += 256) { float v = rp[d]+xp[d]; buf[d]=v; s += v; }
    for (int o=16;o;o>>=1) s += __shfl_xor_sync(0xffffffffu, s, o);
    if ((tid&31)==0) red[tid>>5] = s;
    __syncthreads();
    s = red[0];
    #pragma unroll
    for (int i=1;i<8;i++) s += red[i];
    float mu = s * (1.f/DM);
    float vs = 0.f;
    for (int d = tid; d < DM; d += 256) { float v = buf[d]-mu; vs += v*v; }
    __syncthreads();
    for (int o=16;o;o>>=1) vs += __shfl_xor_sync(0xffffffffu, vs, o);
    if ((tid&31)==0) red[tid>>5] = vs;
    __syncthreads();
    vs = red[0];
    #pragma unroll
    for (int i=1;i<8;i++) vs += red[i];
    float inv = rsqrtf(vs * (1.f/DM) + 1e-5f);
    for (int d = tid; d < DM; d += 256)
        out[(size_t)row*DM + d] = (buf[d]-mu)*inv*g[d] + b[d];
}

// LN2 fused with the router select: skip rows keep old g_h (no write).
__global__ __launch_bounds__(256) void k_lnadd_sel(const float* __restrict__ res,
        const float* __restrict__ x, const float* __restrict__ g,
        const float* __restrict__ b, float* __restrict__ out) {
    int row = blockIdx.x;
    if (g_skip[row]) return;
    const float* rp = res + (size_t)row*DM;
    const float* xp = x   + (size_t)row*DM;
    __shared__ float buf[DM];
    __shared__ float red[8];
    int tid = threadIdx.x;
    float s = 0.f;
    for (int d = tid; d < DM; d += 256) { float v = rp[d]+xp[d]; buf[d]=v; s += v; }
    for (int o=16;o;o>>=1) s += __shfl_xor_sync(0xffffffffu, s, o);
    if ((tid&31)==0) red[tid>>5] = s;
    __syncthreads();
    s = red[0];
    #pragma unroll
    for (int i=1;i<8;i++) s += red[i];
    float mu = s * (1.f/DM);
    float vs = 0.f;
    for (int d = tid; d < DM; d += 256) { float v = buf[d]-mu; vs += v*v; }
    __syncthreads();
    for (int o=16;o;o>>=1) vs += __shfl_xor_sync(0xffffffffu, vs, o);
    if ((tid&31)==0) red[tid>>5] = vs;
    __syncthreads();
    vs = red[0];
    #pragma unroll
    for (int i=1;i<8;i++) vs += red[i];
    float inv = rsqrtf(vs * (1.f/DM) + 1e-5f);
    for (int d = tid; d < DM; d += 256)
        out[(size_t)row*DM + d] = (buf[d]-mu)*inv*g[d] + b[d];
}

__global__ void k_finalize(float* out, int base) {
    float sk = (float)g_cnt[0], fw = (float)g_cnt[1], rc = (float)g_cnt[2];
    float total = (float)(MM * NL);
    out[base+0] = (fw + rc) / (float)MM;   // effective_depth = mean token depth
    out[base+1] = sk / total;
    out[base+2] = fw / total;
    out[base+3] = rc / total;
}

// ---------------- host driver ----------------
extern "C" void kernel_launch(void* const* d_in, const int* in_sizes, int n_in,
                              void* d_out, int out_size) {
    const int*   x    = (const int*)  d_in[0];
    const float* emb  = (const float*)d_in[1];
    const float* Wq   = (const float*)d_in[2],  *bq   = (const float*)d_in[3];
    const float* Wk   = (const float*)d_in[4],  *bk   = (const float*)d_in[5];
    const float* Wv   = (const float*)d_in[6],  *bv   = (const float*)d_in[7];
    const float* Wo   = (const float*)d_in[8],  *bo   = (const float*)d_in[9];
    const float* ln1g = (const float*)d_in[10], *ln1b = (const float*)d_in[11];
    const float* Wf1  = (const float*)d_in[12], *bf1  = (const float*)d_in[13];
    const float* Wf2  = (const float*)d_in[14], *bf2  = (const float*)d_in[15];
    const float* ln2g = (const float*)d_in[16], *ln2b = (const float*)d_in[17];
    const float* rW1  = (const float*)d_in[18], *rb1  = (const float*)d_in[19];
    const float* rW2  = (const float*)d_in[20], *rb2  = (const float*)d_in[21];
    const float* Wout = (const float*)d_in[22], *bout = (const float*)d_in[23];
    float* out = (float*)d_out;

    float *h, *h1, *att, *ff, *t2, *rh;
    cudaGetSymbolAddress((void**)&h,   g_h);
    cudaGetSymbolAddress((void**)&h1,  g_h1);
    cudaGetSymbolAddress((void**)&att, g_att);
    cudaGetSymbolAddress((void**)&ff,  g_ff);
    cudaGetSymbolAddress((void**)&t2,  g_t2);
    cudaGetSymbolAddress((void**)&rh,  g_rh);

    k_reset<<<1,1>>>();
    k_embed<<<MM,256>>>(x, emb);

    dim3 gdd (DM/64,  MM/128);    // 16 x 16  (D x D GEMMs)
    dim3 gqkv(48,     MM/128);    // fused QKV
    dim3 gff1(FFD/64, MM/128);    // 64 x 16
    dim3 grt (RH/64,  MM/128);    // 2 x 16   (router hidden)
    dim3 gsc (16, 16, NZ);
    dim3 gpv (16, 1,  NZ);

    for (int i = 0; i < NL; i++) {
        k_gemm<2><<<grt,256>>>(h, rW1 + (size_t)i*DM*RH, rb1 + (size_t)i*RH, rh, MM, RH, DM);
        k_argmax<<<MM/8,256>>>(rW2 + (size_t)i*RH*3, rb2 + (size_t)i*3);
        k_gemm_qkv<<<gqkv,256>>>(h, Wq, Wk, Wv, bq, bk, bv);
        k_scores<<<gsc,256>>>();
        k_softmax<<<NZ*SS,256>>>();
        k_pv<<<gpv,256>>>();
        k_gemm<0><<<gdd,256>>>(att, Wo, bo, t2, MM, DM, DM);
        k_lnadd<<<MM,256>>>(h, t2, ln1g, ln1b, h1);
        k_gemm<2><<<gff1,256>>>(h1, Wf1, bf1, ff, MM, FFD, DM);
        k_gemm<0><<<gdd,256>>>(ff, Wf2, bf2, t2, MM, DM, FFD);
        k_lnadd_sel<<<MM,256>>>(h1, t2, ln2g, ln2b, h);
    }
    k_gemm<0><<<dim3(32000/64, MM/128),256>>>(h, Wout, bout, out, MM, 32000, DM);
    k_finalize<<<1,1>>>(out, out_size - 4);
}